// round 2
// baseline (speedup 1.0000x reference)
#include <cuda_runtime.h>

// Problem constants (fixed by the reference)
#define B_N 8192
#define C_N 1000
#define D_N 2048
#define CLAMP_MIN 1e-12f
#define CLAMP_MAX 1e12f
#define SEP_W 0.001

// Scratch accumulators (device globals: no allocation allowed)
__device__ double g_sum_xx;        // sum_b ||x_b||^2
__device__ double g_sum_cn;        // sum_c ||c_c||^2
__device__ double g_label_sum;     // sum_b clamp(||x_b||^2 + ||c_lb||^2 - 2 x_b.c_lb)
__device__ float  g_colsum_x[D_N]; // sum_b x[b,:]
__device__ float  g_colsum_c[D_N]; // sum_c centers[c,:]
__device__ float  g_cnorm[C_N];    // per-center squared norms
__device__ int    g_lab64;         // 1 if labels buffer is int64-laid-out

// ---------------------------------------------------------------------------
__global__ void cl_init(const int* __restrict__ labels_i32) {
    int i = blockIdx.x * blockDim.x + threadIdx.x;
    if (i < D_N) { g_colsum_x[i] = 0.f; g_colsum_c[i] = 0.f; }
    if (i == 0) {
        g_sum_xx = 0.0; g_sum_cn = 0.0; g_label_sum = 0.0;
        // Detect int64 layout: odd 32-bit words of little-endian int64 labels
        // (values < 1000) are all zero. For int32 labels, overwhelmingly not.
        int any_odd = 0;
        #pragma unroll 1
        for (int k = 0; k < 64; ++k) any_odd |= labels_i32[2 * k + 1];
        g_lab64 = (any_odd == 0) ? 1 : 0;
    }
}

// ---------------------------------------------------------------------------
// Centers pass: per-center squared norm (stored), global sum of norms,
// column sums. 125 blocks x 256 threads, 8 rows per block.
__global__ void cl_centers(const float* __restrict__ centers) {
    __shared__ float s_red[8];
    const int t = threadIdx.x;
    const int lane = t & 31, warp = t >> 5;
    float4 a0 = make_float4(0.f, 0.f, 0.f, 0.f);
    float4 a1 = make_float4(0.f, 0.f, 0.f, 0.f);
    double cn_acc = 0.0;

    const int base = blockIdx.x * 8;
    #pragma unroll 1
    for (int r = 0; r < 8; ++r) {
        const int row = base + r;
        const float4* cr = (const float4*)(centers + (size_t)row * D_N);
        float4 v0 = cr[t];
        float4 v1 = cr[t + 256];
        a0.x += v0.x; a0.y += v0.y; a0.z += v0.z; a0.w += v0.w;
        a1.x += v1.x; a1.y += v1.y; a1.z += v1.z; a1.w += v1.w;
        float nn = v0.x*v0.x + v0.y*v0.y + v0.z*v0.z + v0.w*v0.w
                 + v1.x*v1.x + v1.y*v1.y + v1.z*v1.z + v1.w*v1.w;
        #pragma unroll
        for (int o = 16; o; o >>= 1) nn += __shfl_down_sync(0xffffffffu, nn, o);
        if (lane == 0) s_red[warp] = nn;
        __syncthreads();
        if (t == 0) {
            float tot = 0.f;
            #pragma unroll
            for (int w = 0; w < 8; ++w) tot += s_red[w];
            g_cnorm[row] = tot;
            cn_acc += (double)tot;
        }
        __syncthreads();
    }
    if (t == 0) atomicAdd(&g_sum_cn, cn_acc);
    const int c0 = 4 * t;
    atomicAdd(&g_colsum_c[c0 + 0], a0.x);
    atomicAdd(&g_colsum_c[c0 + 1], a0.y);
    atomicAdd(&g_colsum_c[c0 + 2], a0.z);
    atomicAdd(&g_colsum_c[c0 + 3], a0.w);
    atomicAdd(&g_colsum_c[1024 + c0 + 0], a1.x);
    atomicAdd(&g_colsum_c[1024 + c0 + 1], a1.y);
    atomicAdd(&g_colsum_c[1024 + c0 + 2], a1.z);
    atomicAdd(&g_colsum_c[1024 + c0 + 3], a1.w);
}

// ---------------------------------------------------------------------------
// X pass: per-row ||x||^2 and x . center[label] (gathered from L2-resident
// centers), clamped label distance, global sums, column sums of x.
// 512 blocks x 256 threads, 16 rows per block.
__global__ void cl_xpass(const float* __restrict__ x,
                         const float* __restrict__ centers,
                         const int* __restrict__ labels_i32) {
    __shared__ float s_xx[8];
    __shared__ float s_xc[8];
    const int t = threadIdx.x;
    const int lane = t & 31, warp = t >> 5;
    const int lab64 = g_lab64;
    float4 a0 = make_float4(0.f, 0.f, 0.f, 0.f);
    float4 a1 = make_float4(0.f, 0.f, 0.f, 0.f);
    double xx_acc = 0.0, lab_acc = 0.0;

    const int base = blockIdx.x * 16;
    #pragma unroll 1
    for (int r = 0; r < 16; ++r) {
        const int row = base + r;
        int lab = lab64 ? labels_i32[2 * row] : labels_i32[row];
        lab = max(0, min(C_N - 1, lab));   // defensive: never OOB
        const float4* xr = (const float4*)(x + (size_t)row * D_N);
        const float4* cr = (const float4*)(centers + (size_t)lab * D_N);
        float4 v0 = xr[t];
        float4 v1 = xr[t + 256];
        float4 c0 = cr[t];
        float4 c1 = cr[t + 256];
        a0.x += v0.x; a0.y += v0.y; a0.z += v0.z; a0.w += v0.w;
        a1.x += v1.x; a1.y += v1.y; a1.z += v1.z; a1.w += v1.w;
        float xx = v0.x*v0.x + v0.y*v0.y + v0.z*v0.z + v0.w*v0.w
                 + v1.x*v1.x + v1.y*v1.y + v1.z*v1.z + v1.w*v1.w;
        float xc = v0.x*c0.x + v0.y*c0.y + v0.z*c0.z + v0.w*c0.w
                 + v1.x*c1.x + v1.y*c1.y + v1.z*c1.z + v1.w*c1.w;
        #pragma unroll
        for (int o = 16; o; o >>= 1) {
            xx += __shfl_down_sync(0xffffffffu, xx, o);
            xc += __shfl_down_sync(0xffffffffu, xc, o);
        }
        if (lane == 0) { s_xx[warp] = xx; s_xc[warp] = xc; }
        __syncthreads();
        if (t == 0) {
            float txx = 0.f, txc = 0.f;
            #pragma unroll
            for (int w = 0; w < 8; ++w) { txx += s_xx[w]; txc += s_xc[w]; }
            float d = txx + g_cnorm[lab] - 2.0f * txc;
            d = fminf(fmaxf(d, CLAMP_MIN), CLAMP_MAX);
            lab_acc += (double)d;
            xx_acc  += (double)txx;
        }
        __syncthreads();
    }
    if (t == 0) {
        atomicAdd(&g_label_sum, lab_acc);
        atomicAdd(&g_sum_xx, xx_acc);
    }
    const int c0i = 4 * t;
    atomicAdd(&g_colsum_x[c0i + 0], a0.x);
    atomicAdd(&g_colsum_x[c0i + 1], a0.y);
    atomicAdd(&g_colsum_x[c0i + 2], a0.z);
    atomicAdd(&g_colsum_x[c0i + 3], a0.w);
    atomicAdd(&g_colsum_x[1024 + c0i + 0], a1.x);
    atomicAdd(&g_colsum_x[1024 + c0i + 1], a1.y);
    atomicAdd(&g_colsum_x[1024 + c0i + 2], a1.z);
    atomicAdd(&g_colsum_x[1024 + c0i + 3], a1.w);
}

// ---------------------------------------------------------------------------
// Finalize: cross = colsum_x . colsum_c, then combine.
__global__ void cl_finalize(float* __restrict__ out) {
    __shared__ double sd[256];
    const int t = threadIdx.x;
    double cross = 0.0;
    #pragma unroll
    for (int d = t; d < D_N; d += 256)
        cross += (double)g_colsum_x[d] * (double)g_colsum_c[d];
    sd[t] = cross;
    __syncthreads();
    #pragma unroll
    for (int s = 128; s; s >>= 1) {
        if (t < s) sd[t] += sd[t + s];
        __syncthreads();
    }
    if (t == 0) {
        const double crossv = sd[0];
        const double total = (double)C_N * g_sum_xx
                           + (double)B_N * g_sum_cn
                           - 2.0 * crossv;
        const double label = g_label_sum;
        const double center_loss = label / (double)B_N;
        const double sep_loss = (total - label) / ((double)B_N * (double)(C_N - 1));
        out[0] = (float)(center_loss - SEP_W * sep_loss);
    }
}

// ---------------------------------------------------------------------------
extern "C" void kernel_launch(void* const* d_in, const int* in_sizes, int n_in,
                              void* d_out, int out_size) {
    const float* x       = (const float*)d_in[0];
    const float* centers = (const float*)d_in[1];
    const int*   labels  = (const int*)d_in[2];
    float* out = (float*)d_out;

    cl_init<<<(D_N + 255) / 256, 256>>>(labels);
    cl_centers<<<C_N / 8, 256>>>(centers);
    cl_xpass<<<B_N / 16, 256>>>(x, centers, labels);
    cl_finalize<<<1, 256>>>(out);
}

// round 3
// speedup vs baseline: 1.7527x; 1.7527x over previous
#include <cuda_runtime.h>

// Problem constants (fixed by the reference)
#define B_N 8192
#define C_N 1000
#define D_N 2048
#define SEP_W 0.001

// Grid layout: x blocks first (long-running), then center blocks.
#define NXB 256
#define ROWS_PER_XB 32          // 256 * 32 = 8192
#define NCB 125
#define ROWS_PER_CB 8           // 125 * 8  = 1000
#define NBLK (NXB + NCB)

// Accumulators. Zero-initialized at module load; cl_finalize re-zeroes them
// after consuming, so every graph replay starts from a clean state.
__device__ double g_sum_xx;         // sum over all elements of x^2
__device__ double g_sum_xc;         // sum_b x_b . c_{label_b}
__device__ float  g_colsum_x[D_N];  // sum_b x[b,:]
__device__ float  g_colsum_c[D_N];  // sum_c centers[c,:]
__device__ float  g_cnorm[C_N];     // per-center squared norms

// Labels may be int64 (reference asks for it) or int32 (JAX default x64=off).
// For int64 little-endian values < 1000, every odd 32-bit word is 0.
__device__ __forceinline__ int detect_lab64(const int* __restrict__ l) {
    int any = 0;
    #pragma unroll
    for (int k = 0; k < 16; ++k) any |= l[2 * k + 1];
    return any == 0;
}

__device__ __forceinline__ float dot4(float4 a, float4 b) {
    return a.x * b.x + a.y * b.y + a.z * b.z + a.w * b.w;
}

// ---------------------------------------------------------------------------
// Main pass: barrier-free streaming. Thread t owns columns [4t,4t+3] and
// [1024+4t, 1024+4t+3] of every row its block touches.
__global__ void __launch_bounds__(256, 4)
cl_main(const float* __restrict__ x,
        const float* __restrict__ centers,
        const int* __restrict__ labels_i32) {
    const int t = threadIdx.x;
    const int lane = t & 31, warp = t >> 5;

    if (blockIdx.x < NXB) {
        // ------------------------- X blocks -------------------------------
        const int lab64 = detect_lab64(labels_i32);
        const int base = blockIdx.x * ROWS_PER_XB;
        float4 a0 = make_float4(0.f, 0.f, 0.f, 0.f);
        float4 a1 = make_float4(0.f, 0.f, 0.f, 0.f);
        float xx = 0.f, xc = 0.f;

        #pragma unroll 4
        for (int r = 0; r < ROWS_PER_XB; ++r) {
            const int row = base + r;
            int lab = lab64 ? labels_i32[2 * row] : labels_i32[row];
            lab = max(0, min(C_N - 1, lab));          // defensive: never OOB
            const float4* xr = (const float4*)(x + (size_t)row * D_N);
            const float4* cr = (const float4*)(centers + (size_t)lab * D_N);
            float4 v0 = xr[t];
            float4 v1 = xr[t + 256];
            float4 c0 = cr[t];
            float4 c1 = cr[t + 256];
            a0.x += v0.x; a0.y += v0.y; a0.z += v0.z; a0.w += v0.w;
            a1.x += v1.x; a1.y += v1.y; a1.z += v1.z; a1.w += v1.w;
            xx += dot4(v0, v0) + dot4(v1, v1);
            xc += dot4(v0, c0) + dot4(v1, c1);
        }

        // One block reduction at the very end (sole barrier in this kernel).
        __shared__ float s_xx[8], s_xc[8];
        #pragma unroll
        for (int o = 16; o; o >>= 1) {
            xx += __shfl_down_sync(0xffffffffu, xx, o);
            xc += __shfl_down_sync(0xffffffffu, xc, o);
        }
        if (lane == 0) { s_xx[warp] = xx; s_xc[warp] = xc; }
        __syncthreads();
        if (t == 0) {
            float txx = 0.f, txc = 0.f;
            #pragma unroll
            for (int w = 0; w < 8; ++w) { txx += s_xx[w]; txc += s_xc[w]; }
            atomicAdd(&g_sum_xx, (double)txx);
            atomicAdd(&g_sum_xc, (double)txc);
        }
        const int c0i = 4 * t;
        atomicAdd(&g_colsum_x[c0i + 0], a0.x);
        atomicAdd(&g_colsum_x[c0i + 1], a0.y);
        atomicAdd(&g_colsum_x[c0i + 2], a0.z);
        atomicAdd(&g_colsum_x[c0i + 3], a0.w);
        atomicAdd(&g_colsum_x[1024 + c0i + 0], a1.x);
        atomicAdd(&g_colsum_x[1024 + c0i + 1], a1.y);
        atomicAdd(&g_colsum_x[1024 + c0i + 2], a1.z);
        atomicAdd(&g_colsum_x[1024 + c0i + 3], a1.w);
    } else {
        // ----------------------- Center blocks ----------------------------
        const int base = (blockIdx.x - NXB) * ROWS_PER_CB;
        float4 a0 = make_float4(0.f, 0.f, 0.f, 0.f);
        float4 a1 = make_float4(0.f, 0.f, 0.f, 0.f);

        #pragma unroll 2
        for (int r = 0; r < ROWS_PER_CB; ++r) {
            const int row = base + r;
            const float4* cr = (const float4*)(centers + (size_t)row * D_N);
            float4 v0 = cr[t];
            float4 v1 = cr[t + 256];
            a0.x += v0.x; a0.y += v0.y; a0.z += v0.z; a0.w += v0.w;
            a1.x += v1.x; a1.y += v1.y; a1.z += v1.z; a1.w += v1.w;
            float nn = dot4(v0, v0) + dot4(v1, v1);
            #pragma unroll
            for (int o = 16; o; o >>= 1)
                nn += __shfl_down_sync(0xffffffffu, nn, o);
            if (lane == 0) atomicAdd(&g_cnorm[row], nn);  // 8 adds per center
        }
        const int c0i = 4 * t;
        atomicAdd(&g_colsum_c[c0i + 0], a0.x);
        atomicAdd(&g_colsum_c[c0i + 1], a0.y);
        atomicAdd(&g_colsum_c[c0i + 2], a0.z);
        atomicAdd(&g_colsum_c[c0i + 3], a0.w);
        atomicAdd(&g_colsum_c[1024 + c0i + 0], a1.x);
        atomicAdd(&g_colsum_c[1024 + c0i + 1], a1.y);
        atomicAdd(&g_colsum_c[1024 + c0i + 2], a1.z);
        atomicAdd(&g_colsum_c[1024 + c0i + 3], a1.w);
    }
}

// ---------------------------------------------------------------------------
// Finalize: label histogram, cross term, combine, and RESET all accumulators
// to zero so the next graph replay starts clean.
__global__ void cl_finalize(const int* __restrict__ labels_i32,
                            float* __restrict__ out) {
    __shared__ int hist[C_N];
    __shared__ double sd[3][8];
    const int t = threadIdx.x;
    const int lane = t & 31, warp = t >> 5;

    for (int c = t; c < C_N; c += 256) hist[c] = 0;
    __syncthreads();

    const int lab64 = detect_lab64(labels_i32);
    for (int i = t; i < B_N; i += 256) {
        int lab = lab64 ? labels_i32[2 * i] : labels_i32[i];
        lab = max(0, min(C_N - 1, lab));
        atomicAdd(&hist[lab], 1);
    }
    __syncthreads();

    double cross = 0.0, cnw = 0.0, cnsum = 0.0;
    for (int d = t; d < D_N; d += 256) {
        cross += (double)g_colsum_x[d] * (double)g_colsum_c[d];
        g_colsum_x[d] = 0.f;
        g_colsum_c[d] = 0.f;
    }
    for (int c = t; c < C_N; c += 256) {
        double cn = (double)g_cnorm[c];
        cnw   += cn * (double)hist[c];
        cnsum += cn;
        g_cnorm[c] = 0.f;
    }

    #pragma unroll
    for (int o = 16; o; o >>= 1) {
        cross += __shfl_down_sync(0xffffffffu, cross, o);
        cnw   += __shfl_down_sync(0xffffffffu, cnw, o);
        cnsum += __shfl_down_sync(0xffffffffu, cnsum, o);
    }
    if (lane == 0) { sd[0][warp] = cross; sd[1][warp] = cnw; sd[2][warp] = cnsum; }
    __syncthreads();

    if (t == 0) {
        double tc = 0.0, tw = 0.0, ts = 0.0;
        #pragma unroll
        for (int w = 0; w < 8; ++w) { tc += sd[0][w]; tw += sd[1][w]; ts += sd[2][w]; }
        const double sum_xx = g_sum_xx;  g_sum_xx = 0.0;
        const double sum_xc = g_sum_xc;  g_sum_xc = 0.0;

        // label-path sum (clamp provably inactive: d ~ 4096 >> 1e-12)
        const double label_sum = sum_xx + tw - 2.0 * sum_xc;
        // full distmat sum
        const double total = (double)C_N * sum_xx + (double)B_N * ts - 2.0 * tc;

        const double center_loss = label_sum / (double)B_N;
        const double sep_loss = (total - label_sum) / ((double)B_N * (double)(C_N - 1));
        out[0] = (float)(center_loss - SEP_W * sep_loss);
    }
}

// ---------------------------------------------------------------------------
extern "C" void kernel_launch(void* const* d_in, const int* in_sizes, int n_in,
                              void* d_out, int out_size) {
    const float* x       = (const float*)d_in[0];
    const float* centers = (const float*)d_in[1];
    const int*   labels  = (const int*)d_in[2];
    float* out = (float*)d_out;

    cl_main<<<NBLK, 256>>>(x, centers, labels);
    cl_finalize<<<1, 256>>>(labels, out);
}